// round 7
// baseline (speedup 1.0000x reference)
#include <cuda_runtime.h>
#include <cuda_fp16.h>
#include <cstdint>

#define N_NODES 8192
#define IN_F 256
#define OUT_F 64
#define ALPHA 0.3f
#define LOG2E 1.4426950408889634f
#define JSPLIT 16
#define JSPAN 512         // columns per block
#define ROWTILE 128
#define KCH 64            // columns per chunk
#define NCH 8             // JSPAN/KCH
#define NWHBLK 256        // wh blocks (32 rows each)

// ---- attn dynamic SMEM layout (bytes) ----
#define PROWB 520         // B row stride in halves (1040 B; bank step 4, 16B-aligned)
#define PROWP 72          // P row stride in halves (144 B)
#define ADJSTR 68         // adj row stride in floats (272 B)
#define OFF_B   0                       // 64 x 520 halves   = 66560
#define OFF_ADJ 66560                   // 8 w x 2 buf x 4352 = 69632
#define OFF_P   136192                  // 8 w x 2304         = 18432
#define OFF_DST 154624                  // 512 floats         = 2048
#define SMEM_ATTN 156672

// ---- wh dynamic SMEM layout (bytes) ----
#define WOFF_W  0                       // 256x64 f32 = 65536
#define WOFF_H  65536                   // 32x264 f32 = 33792
#define WOFF_WH 99328                   // 64x40 half = 5120
#define WOFF_DT 104448                  // 32 f32     = 128
#define SMEM_WH 104576

// ---------------- device scratch (no allocations allowed) ----------------
__device__ __half g_WhT[OUT_F * N_NODES];            // Wh^T fp16 [64][8192]
__device__ float g_src[N_NODES];
__device__ float g_dst[N_NODES];
__device__ float g_blockmax[NWHBLK];
__device__ float g_pacc[JSPLIT][N_NODES][OUT_F];     // 32 MB fp32 partials
__device__ float g_pden[JSPLIT][N_NODES];

__device__ __forceinline__ uint32_t smem_u32(const void* p) {
    uint32_t a;
    asm("{ .reg .u64 t; cvta.to.shared.u64 t, %1; cvt.u32.u64 %0, t; }" : "=r"(a) : "l"(p));
    return a;
}
__device__ __forceinline__ void cp16(uint32_t s, const void* g) {
    asm volatile("cp.async.cg.shared.global [%0], [%1], 16;" :: "r"(s), "l"(g));
}
#define CP_COMMIT()  asm volatile("cp.async.commit_group;" ::: "memory")
#define CP_WAIT1()   asm volatile("cp.async.wait_group 1;" ::: "memory")
__device__ __forceinline__ float ex2f(float x) {
    float r;
    asm("ex2.approx.f32 %0, %1;" : "=f"(r) : "f"(x));
    return r;
}
__device__ __forceinline__ void ldmatrix_x4(uint32_t& r0, uint32_t& r1, uint32_t& r2,
                                            uint32_t& r3, uint32_t addr) {
    asm volatile("ldmatrix.sync.aligned.m8n8.x4.shared.b16 {%0,%1,%2,%3}, [%4];"
                 : "=r"(r0), "=r"(r1), "=r"(r2), "=r"(r3) : "r"(addr));
}
__device__ __forceinline__ void mma_16816(float* c, uint32_t a0, uint32_t a1,
                                          uint32_t a2, uint32_t a3,
                                          uint32_t b0, uint32_t b1) {
    asm volatile(
        "mma.sync.aligned.m16n8k16.row.col.f32.f16.f16.f32 "
        "{%0,%1,%2,%3}, {%4,%5,%6,%7}, {%8,%9}, {%0,%1,%2,%3};"
        : "+f"(c[0]), "+f"(c[1]), "+f"(c[2]), "+f"(c[3])
        : "r"(a0), "r"(a1), "r"(a2), "r"(a3), "r"(b0), "r"(b1));
}

// ---------------------------------------------------------------------------
// Kernel 1: Wh = h @ W; WhT fp16 [64][8192], src/dst fp32, per-block dst max.
// Grid 256 (32 rows/block), 256 threads. Whole W resident in SMEM (one load);
// thread = 1 row x 8 feats. W reads dedup to warp broadcast -> conflict-free.
// ---------------------------------------------------------------------------
__global__ __launch_bounds__(256, 2) void wh_kernel(const float* __restrict__ h,
                                                    const float* __restrict__ W,
                                                    const float* __restrict__ a) {
    extern __shared__ char wsm[];
    float* sW = reinterpret_cast<float*>(wsm + WOFF_W);       // [k*64 + f]
    float* sh = reinterpret_cast<float*>(wsm + WOFF_H);       // [row*264 + k]
    __half* sWh = reinterpret_cast<__half*>(wsm + WOFF_WH);   // [f*40 + row]
    float* dtile = reinterpret_cast<float*>(wsm + WOFF_DT);

    const int tid = threadIdx.x;
    const int I0 = blockIdx.x * 32;

    // W: 4096 float4 slots
#pragma unroll
    for (int it = 0; it < 16; it++) {
        const int idx = tid + it * 256;
        *reinterpret_cast<float4*>(&sW[idx * 4]) =
            __ldg(reinterpret_cast<const float4*>(W) + idx);
    }
    // h tile: 2048 float4 slots, row stride 264
#pragma unroll
    for (int it = 0; it < 8; it++) {
        const int idx = tid + it * 256;
        const int r = idx >> 6, c = idx & 63;
        *reinterpret_cast<float4*>(&sh[r * 264 + c * 4]) =
            __ldg(reinterpret_cast<const float4*>(&h[(size_t)(I0 + r) * IN_F]) + c);
    }
    __syncthreads();

    const int row = tid >> 3;
    const int f0 = (tid & 7) * 8;
    float acc[8] = {};
#pragma unroll 8
    for (int k = 0; k < IN_F; k++) {
        const float hv = sh[row * 264 + k];
        const float4 wa = *reinterpret_cast<const float4*>(&sW[k * 64 + f0]);
        const float4 wb = *reinterpret_cast<const float4*>(&sW[k * 64 + f0 + 4]);
        acc[0] += hv * wa.x; acc[1] += hv * wa.y; acc[2] += hv * wa.z; acc[3] += hv * wa.w;
        acc[4] += hv * wb.x; acc[5] += hv * wb.y; acc[6] += hv * wb.z; acc[7] += hv * wb.w;
    }

#pragma unroll
    for (int j = 0; j < 8; j++) sWh[(f0 + j) * 40 + row] = __float2half(acc[j]);

    float sp = 0.f, dp = 0.f;
#pragma unroll
    for (int j = 0; j < 8; j++) {
        sp += acc[j] * __ldg(&a[f0 + j]);
        dp += acc[j] * __ldg(&a[OUT_F + f0 + j]);
    }
#pragma unroll
    for (int o = 1; o < 8; o <<= 1) {
        sp += __shfl_xor_sync(0xffffffffu, sp, o);
        dp += __shfl_xor_sync(0xffffffffu, dp, o);
    }
    if ((tid & 7) == 0) {
        g_src[I0 + row] = sp;
        g_dst[I0 + row] = dp;
        dtile[row] = dp;
    }
    __syncthreads();
    {   // coalesced WhT store: f = tid>>2, 8-half quarter
        const int f = tid >> 2, q = tid & 3;
        *reinterpret_cast<uint4*>(&g_WhT[(size_t)f * N_NODES + I0 + q * 8]) =
            *reinterpret_cast<const uint4*>(&sWh[f * 40 + q * 8]);
    }
    if (tid == 0) {
        float mm = dtile[0];
        for (int q = 1; q < 32; q++) mm = fmaxf(mm, dtile[q]);
        g_blockmax[blockIdx.x] = mm;
    }
}

// ---------------------------------------------------------------------------
// Kernel 2: masked dense attention GEMM, warp-autonomous pipeline.
// Block = 128 rows x 512 cols (grid 64 x 16 = 1024), 256 threads.
// B tile (WhT slice, 64x512 fp16) loaded once; then each warp owns rows
// 16w..16w+15: private cp.async double-buffered adj chunks, private P tile,
// ldmatrix+HMMA into registers. NO __syncthreads in the mainloop.
// ---------------------------------------------------------------------------
__global__ __launch_bounds__(256) void attn_kernel(const float* __restrict__ adj) {
    extern __shared__ char dsm[];
    __shared__ float sBm[8];
    __shared__ float sDmax;

    const uint32_t base = smem_u32(dsm);
    float* const sDst = reinterpret_cast<float*>(dsm + OFF_DST);

    const int tid = threadIdx.x;
    const int w = tid >> 5, lane = tid & 31;
    const int row = lane >> 1, half = lane & 1;   // warp-local P/adj mapping
    const int rt = blockIdx.x >> 4, js = blockIdx.x & 15;
    const int I0 = rt * ROWTILE;
    const int jbase = js * JSPAN;

    const uint32_t adjB0 = base + OFF_ADJ + w * 8704;
    const uint32_t adjB1 = adjB0 + 4352;
    const char* const adjP0 = dsm + OFF_ADJ + w * 8704;
    const char* const adjP1 = adjP0 + 4352;
    const uint32_t pW = base + OFF_P + w * 2304;

    const size_t gRowOff = (size_t)(I0 + 16 * w + row) * N_NODES + jbase + half * 32;
    const uint32_t sRowOff = (uint32_t)(row * ADJSTR + half * 32) * 4;

    // ---- prime chunk 0 (warp-private adj) ----
#pragma unroll
    for (int j = 0; j < 8; j++)
        cp16(adjB0 + sRowOff + j * 16, &adj[gRowOff + j * 4]);
    CP_COMMIT();

    // ---- B tile: WhT[64][jbase..+512] -> SMEM, stride PROWB ----
#pragma unroll
    for (int it = 0; it < 16; it++) {
        const int idx = tid + it * 256;          // 4096 16B slots
        const int f = idx >> 6, slot = idx & 63;
        *reinterpret_cast<uint4*>(dsm + OFF_B + (f * PROWB + slot * 8) * 2) =
            __ldg(reinterpret_cast<const uint4*>(&g_WhT[(size_t)f * N_NODES + jbase]) + slot);
    }
    // dst slice
    if (tid < 128)
        *reinterpret_cast<float4*>(&sDst[tid * 4]) =
            __ldg(reinterpret_cast<const float4*>(&g_dst[jbase]) + tid);
    // dmax
    {
        float m = g_blockmax[tid];
#pragma unroll
        for (int o = 16; o; o >>= 1) m = fmaxf(m, __shfl_xor_sync(0xffffffffu, m, o));
        if (lane == 0) sBm[w] = m;
    }
    __syncthreads();
    if (tid == 0) {
        float mm = sBm[0];
        for (int s = 1; s < 8; s++) mm = fmaxf(mm, sBm[s]);
        sDmax = mm;
    }
    __syncthreads();

    const float sv = __ldg(&g_src[I0 + 16 * w + row]);
    float px = sv + sDmax;
    px = fmaxf(px, ALPHA * px);
    const float px14 = px * LOG2E;

    // ldmatrix fragment addresses (pattern proven in R5)
    const uint32_t aAddr = pW + ((lane & 15) * PROWP + (lane >> 4) * 8) * 2;
    const uint32_t bRow = (lane & 7) + ((lane & 16) ? 8 : 0);
    const uint32_t bKoff = (lane & 8) ? 8 : 0;
    const uint32_t bFrag = base + OFF_B + (bRow * PROWB + bKoff) * 2;

    float acc[8][4] = {};
    float den = 0.f;

    for (int ch = 0; ch < NCH; ch++) {
        const int buf = ch & 1;
        // issue ch+1 into the other buffer (warp-private)
        if (ch + 1 < NCH) {
            const uint32_t dst = buf ? adjB0 : adjB1;
            const size_t g0 = gRowOff + (ch + 1) * KCH;
#pragma unroll
            for (int j = 0; j < 8; j++)
                cp16(dst + sRowOff + j * 16, &adj[g0 + j * 4]);
        }
        CP_COMMIT();
        CP_WAIT1();           // per-thread: chunk ch resident
        __syncwarp();

        // ---- P-gen: lane covers (row, half*32 + 0..31) ----
        const float* sA = reinterpret_cast<const float*>(
            (buf ? adjP1 : adjP0)) + row * ADJSTR + half * 32;
        const float* dp = sDst + ch * KCH + half * 32;
#pragma unroll
        for (int i = 0; i < 8; i++) {
            const float4 av = *reinterpret_cast<const float4*>(&sA[i * 4]);
            const float4 dv = *reinterpret_cast<const float4*>(&dp[i * 4]);
            float e0 = sv + dv.x, e1 = sv + dv.y, e2 = sv + dv.z, e3 = sv + dv.w;
            e0 = fmaxf(e0, ALPHA * e0);  e1 = fmaxf(e1, ALPHA * e1);
            e2 = fmaxf(e2, ALPHA * e2);  e3 = fmaxf(e3, ALPHA * e3);
            const float p0 = av.x * ex2f(fmaf(e0, LOG2E, -px14));
            const float p1 = av.y * ex2f(fmaf(e1, LOG2E, -px14));
            const float p2 = av.z * ex2f(fmaf(e2, LOG2E, -px14));
            const float p3 = av.w * ex2f(fmaf(e3, LOG2E, -px14));
            den += (p0 + p1) + (p2 + p3);
            const __half2 h01 = __floats2half2_rn(p0, p1);
            const __half2 h23 = __floats2half2_rn(p2, p3);
            uint2 pk;
            pk.x = *reinterpret_cast<const uint32_t*>(&h01);
            pk.y = *reinterpret_cast<const uint32_t*>(&h23);
            *reinterpret_cast<uint2*>(dsm + OFF_P + w * 2304 +
                                      (row * PROWP + half * 32 + i * 4) * 2) = pk;
        }
        __syncwarp();

        // ---- MMA: D[16 rows][64 feats] += P * B^T ----
#pragma unroll
        for (int kk = 0; kk < 4; kk++) {
            uint32_t a0, a1, a2, a3;
            ldmatrix_x4(a0, a1, a2, a3, aAddr + kk * 32);
            const uint32_t bc = bFrag + (ch * KCH + kk * 16) * 2;
#pragma unroll
            for (int np = 0; np < 4; np++) {
                uint32_t b0, b1, b2, b3;
                ldmatrix_x4(b0, b1, b2, b3, bc + np * 16 * PROWB * 2);
                mma_16816(acc[2 * np],     a0, a1, a2, a3, b0, b1);
                mma_16816(acc[2 * np + 1], a0, a1, a2, a3, b2, b3);
            }
        }
        __syncwarp();
    }

    // ---- den: pair-reduce (2 lanes per row) ----
    den += __shfl_xor_sync(0xffffffffu, den, 1);
    if (half == 0) g_pden[js][I0 + 16 * w + row] = den;

    // ---- D epilogue (fragment layout) ----
    {
        const int g = lane >> 2, t = lane & 3;
        const int row0 = I0 + 16 * w + g;
#pragma unroll
        for (int nt = 0; nt < 8; nt++) {
            const int col = nt * 8 + t * 2;
            *reinterpret_cast<float2*>(&g_pacc[js][row0][col]) =
                make_float2(acc[nt][0], acc[nt][1]);
            *reinterpret_cast<float2*>(&g_pacc[js][row0 + 8][col]) =
                make_float2(acc[nt][2], acc[nt][3]);
        }
    }
}

// ---------------------------------------------------------------------------
// Kernel 3: combine J-split partials, normalize, ELU.
// ---------------------------------------------------------------------------
__global__ __launch_bounds__(256) void combine_kernel(float* __restrict__ out) {
    const int idx = blockIdx.x * 256 + threadIdx.x;  // over 8192*64
    const int i = idx >> 6, f = idx & 63;
    float sum = 0.f, d = 0.f;
#pragma unroll
    for (int js = 0; js < JSPLIT; js++) {
        sum += g_pacc[js][i][f];
        d   += g_pden[js][i];
    }
    const float v = sum / d;
    out[idx] = v > 0.f ? v : expm1f(v);
}

// ---------------------------------------------------------------------------
// inputs: h [8192,256] f32, adj [8192,8192] f32, W [256,64] f32, a [128,1] f32
// output: [8192,64] f32
// ---------------------------------------------------------------------------
extern "C" void kernel_launch(void* const* d_in, const int* in_sizes, int n_in,
                              void* d_out, int out_size) {
    const float* h   = (const float*)d_in[0];
    const float* adj = (const float*)d_in[1];
    const float* W   = (const float*)d_in[2];
    const float* a   = (const float*)d_in[3];
    float* out = (float*)d_out;

    static int attr_done = 0;
    if (!attr_done) {
        cudaFuncSetAttribute(attn_kernel, cudaFuncAttributeMaxDynamicSharedMemorySize,
                             SMEM_ATTN);
        cudaFuncSetAttribute(wh_kernel, cudaFuncAttributeMaxDynamicSharedMemorySize,
                             SMEM_WH);
        attr_done = 1;
    }

    wh_kernel<<<NWHBLK, 256, SMEM_WH>>>(h, W, a);
    attn_kernel<<<(N_NODES / ROWTILE) * JSPLIT, 256, SMEM_ATTN>>>(adj);
    combine_kernel<<<(N_NODES * OUT_F) / 256, 256>>>(out);
}

// round 8
// speedup vs baseline: 1.6801x; 1.6801x over previous
#include <cuda_runtime.h>
#include <cuda_fp16.h>
#include <cstdint>

#define N_NODES 8192
#define IN_F 256
#define OUT_F 64
#define ALPHA 0.3f
#define LOG2E 1.4426950408889634f
#define MAXNZ 1024
#define NWHBLK 256   // 32 rows per block

// ---------------- device scratch (no allocations allowed) ----------------
__device__ __half g_Whh[N_NODES * OUT_F];   // Wh fp16 [8192][64], 1 MB (L2-resident)
__device__ float g_src[N_NODES];
__device__ float g_dst[N_NODES];
__device__ float g_blockmax[NWHBLK];

__device__ __forceinline__ float ex2f(float x) {
    float r;
    asm("ex2.approx.f32 %0, %1;" : "=f"(r) : "f"(x));
    return r;
}

// ---------------------------------------------------------------------------
// Kernel 1: Wh = h @ W (fp16 out), src/dst projections, per-block dst max.
// Tiled GEMM: block = 32 rows x 64 feats, 256 threads, thread = 2 rows x 4 feats.
// Grid 256 -> ~ 2 blocks/SM wave-balanced, 25 KB smem.
// ---------------------------------------------------------------------------
__global__ __launch_bounds__(256) void wh_kernel(const float* __restrict__ h,
                                                 const float* __restrict__ W,
                                                 const float* __restrict__ a) {
    __shared__ float sh[32][68];    // h tile, padded
    __shared__ float sW[64][64];    // W tile (k-major)
    __shared__ float dtile[32];
    const int tid = threadIdx.x;
    const int tx = tid & 15;        // feat group (4 feats)
    const int ty = tid >> 4;        // row pair (rows 2ty, 2ty+1)
    const int I0 = blockIdx.x * 32;

    float acc0[4] = {}, acc1[4] = {};

    for (int kt = 0; kt < 4; kt++) {
        __syncthreads();
#pragma unroll
        for (int it = 0; it < 2; it++) {       // h tile: 512 float4 slots
            const int s = tid + it * 256;
            const int r = s >> 4, c = (s & 15) << 2;
            *reinterpret_cast<float4*>(&sh[r][c]) = *reinterpret_cast<const float4*>(
                &h[(size_t)(I0 + r) * IN_F + kt * 64 + c]);
        }
#pragma unroll
        for (int it = 0; it < 4; it++) {       // W tile: 1024 float4 slots
            const int s = tid + it * 256;
            const int r = s >> 4, c = (s & 15) << 2;
            *reinterpret_cast<float4*>(&sW[r][c]) = *reinterpret_cast<const float4*>(
                &W[(size_t)(kt * 64 + r) * OUT_F + c]);
        }
        __syncthreads();
#pragma unroll 4
        for (int k = 0; k < 64; k++) {
            const float4 wv = *reinterpret_cast<const float4*>(&sW[k][tx << 2]);
            const float h0 = sh[ty * 2][k], h1 = sh[ty * 2 + 1][k];
            acc0[0] += h0 * wv.x; acc0[1] += h0 * wv.y; acc0[2] += h0 * wv.z; acc0[3] += h0 * wv.w;
            acc1[0] += h1 * wv.x; acc1[1] += h1 * wv.y; acc1[2] += h1 * wv.z; acc1[3] += h1 * wv.w;
        }
    }

    // fp16 Wh stores: 4 halves (8B) per row per thread, coalesced across tx
    {
        const __half2 r0a = __floats2half2_rn(acc0[0], acc0[1]);
        const __half2 r0b = __floats2half2_rn(acc0[2], acc0[3]);
        const __half2 r1a = __floats2half2_rn(acc1[0], acc1[1]);
        const __half2 r1b = __floats2half2_rn(acc1[2], acc1[3]);
        uint2 s0, s1;
        s0.x = *reinterpret_cast<const uint32_t*>(&r0a);
        s0.y = *reinterpret_cast<const uint32_t*>(&r0b);
        s1.x = *reinterpret_cast<const uint32_t*>(&r1a);
        s1.y = *reinterpret_cast<const uint32_t*>(&r1b);
        *reinterpret_cast<uint2*>(&g_Whh[(size_t)(I0 + ty * 2) * OUT_F + tx * 4]) = s0;
        *reinterpret_cast<uint2*>(&g_Whh[(size_t)(I0 + ty * 2 + 1) * OUT_F + tx * 4]) = s1;
    }

    const float4 as = *reinterpret_cast<const float4*>(&a[tx << 2]);
    const float4 ad = *reinterpret_cast<const float4*>(&a[OUT_F + (tx << 2)]);
    float sp0 = acc0[0] * as.x + acc0[1] * as.y + acc0[2] * as.z + acc0[3] * as.w;
    float dp0 = acc0[0] * ad.x + acc0[1] * ad.y + acc0[2] * ad.z + acc0[3] * ad.w;
    float sp1 = acc1[0] * as.x + acc1[1] * as.y + acc1[2] * as.z + acc1[3] * as.w;
    float dp1 = acc1[0] * ad.x + acc1[1] * ad.y + acc1[2] * ad.z + acc1[3] * ad.w;
#pragma unroll
    for (int o = 1; o < 16; o <<= 1) {   // reduce across the 16-lane tx group
        sp0 += __shfl_xor_sync(0xffffffffu, sp0, o);
        dp0 += __shfl_xor_sync(0xffffffffu, dp0, o);
        sp1 += __shfl_xor_sync(0xffffffffu, sp1, o);
        dp1 += __shfl_xor_sync(0xffffffffu, dp1, o);
    }
    if (tx == 0) {
        g_src[I0 + ty * 2] = sp0;     g_src[I0 + ty * 2 + 1] = sp1;
        g_dst[I0 + ty * 2] = dp0;     g_dst[I0 + ty * 2 + 1] = dp1;
        dtile[ty * 2] = dp0;          dtile[ty * 2 + 1] = dp1;
    }
    __syncthreads();
    if (tid == 0) {
        float mm = dtile[0];
        for (int q = 1; q < 32; q++) mm = fmaxf(mm, dtile[q]);
        g_blockmax[blockIdx.x] = mm;
    }
}

// ---------------------------------------------------------------------------
// Kernel 2: fused masked attention + aggregation + ELU. One block per row i.
//   A: 8 batched float4 adj loads (MLP=8) -> ballots -> 256-word bitmask.
//      (dmax reduction overlaps the load latency.)
//   compaction: deterministic prefix-scan -> dense jlist (uniform, no divergence)
//   C: single-pass gather with inline proxy-softmax:
//      p = ex2(lrelu(src_i + dst_j)*log2e - px14); acc += p * Whh[j] (fp16)
// ---------------------------------------------------------------------------
__global__ __launch_bounds__(256) void attn_kernel(const float* __restrict__ adj,
                                                   float* __restrict__ out) {
    const int i = blockIdx.x;
    const int tid = threadIdx.x;
    const int w = tid >> 5;
    const int lane = tid & 31;

    __shared__ unsigned mask[256];
    __shared__ int wsum[8], wbase[8];
    __shared__ float fred[8];
    __shared__ int cnt_s;
    __shared__ float dmax_s, den_s;
    __shared__ unsigned short jlist[MAXNZ];
    __shared__ float acc_red[32][OUT_F];
    __shared__ float fin[4][OUT_F];

    const float4* adj4 = reinterpret_cast<const float4*>(adj + (size_t)i * N_NODES);

    // ---- Phase A: issue all 8 adj loads (MLP=8) ----
    float4 v[8];
#pragma unroll
    for (int k = 0; k < 8; k++) v[k] = __ldg(&adj4[k * 256 + tid]);

    // ---- dmax reduction (overlaps adj load latency) ----
    {
        float m = g_blockmax[tid];
#pragma unroll
        for (int o = 16; o; o >>= 1) m = fmaxf(m, __shfl_xor_sync(0xffffffffu, m, o));
        if (lane == 0) fred[w] = m;
    }
    const float srci = __ldg(&g_src[i]);

    // ---- ballots -> bitmask (word layout identical to R2) ----
#pragma unroll
    for (int k = 0; k < 8; k++) {
        const unsigned b0 = __ballot_sync(0xffffffffu, v[k].x != 0.f);
        const unsigned b1 = __ballot_sync(0xffffffffu, v[k].y != 0.f);
        const unsigned b2 = __ballot_sync(0xffffffffu, v[k].z != 0.f);
        const unsigned b3 = __ballot_sync(0xffffffffu, v[k].w != 0.f);
        if (lane == 0) {
            const int wi = (k * 8 + w) << 2;
            mask[wi + 0] = b0; mask[wi + 1] = b1;
            mask[wi + 2] = b2; mask[wi + 3] = b3;
        }
    }
    __syncthreads();
    if (tid == 0) {
        float mm = fred[0];
        for (int q = 1; q < 8; q++) mm = fmaxf(mm, fred[q]);
        dmax_s = mm;
    }

    // ---- deterministic compaction: exclusive scan of per-word popcounts ----
    const unsigned myword = mask[tid];
    const int c = __popc(myword);
    int incl = c;
#pragma unroll
    for (int o = 1; o < 32; o <<= 1) {
        const int x = __shfl_up_sync(0xffffffffu, incl, o);
        if (lane >= o) incl += x;
    }
    if (lane == 31) wsum[w] = incl;
    __syncthreads();
    if (tid == 0) {
        int run = 0;
        for (int q = 0; q < 8; q++) { wbase[q] = run; run += wsum[q]; }
        cnt_s = run < MAXNZ ? run : MAXNZ;
    }
    __syncthreads();
    {
        // word tid: k = tid>>5, w' = (tid>>2)&7, comp = tid&3
        const int basej = ((tid >> 5) << 10) + (((tid >> 2) & 7) << 7) + (tid & 3);
        int off = wbase[w] + incl - c;
        unsigned m = myword;
        while (m) {
            const int b = __ffs(m) - 1;
            m &= m - 1;
            if (off < MAXNZ) jlist[off] = (unsigned short)(basej + (b << 2));
            off++;
        }
    }
    __syncthreads();
    const int cnt = cnt_s;

    // proxy upper bound: px >= lrelu(src_i + dst_j) for all j
    float px = srci + dmax_s;
    px = fmaxf(px, ALPHA * px);
    const float px14 = px * LOG2E;

    // ---- Phase C: gather with inline p (fp16 Whh rows, fp32 acc, unroll x2) ----
    const int g = lane >> 3;   // 4 nz-groups per warp
    const int s8 = lane & 7;   // 8 lanes x 8 halves = 64 features
    const uint4* whh4 = reinterpret_cast<const uint4*>(g_Whh);
    float acc[8] = {};
    float den = 0.f;

    for (int base = (w << 2); base < cnt; base += 64) {
        const int idx0 = base + g;
        const int idx1 = base + 32 + g;
        int j0 = 0, j1 = 0;
        bool ok0 = idx0 < cnt, ok1 = idx1 < cnt;
        if (ok0) j0 = jlist[idx0];
        if (ok1) j1 = jlist[idx1];
        const float d0 = __ldg(&g_dst[j0]);
        const float d1 = __ldg(&g_dst[j1]);
        const uint4 v0 = __ldg(&whh4[j0 * 8 + s8]);
        const uint4 v1 = __ldg(&whh4[j1 * 8 + s8]);
        float e0 = srci + d0, e1 = srci + d1;
        e0 = fmaxf(e0, ALPHA * e0);
        e1 = fmaxf(e1, ALPHA * e1);
        float p0 = ok0 ? ex2f(fmaf(e0, LOG2E, -px14)) : 0.f;
        float p1 = ok1 ? ex2f(fmaf(e1, LOG2E, -px14)) : 0.f;
        den += p0 + p1;
        const __half2* h0 = reinterpret_cast<const __half2*>(&v0);
        const __half2* h1 = reinterpret_cast<const __half2*>(&v1);
#pragma unroll
        for (int q = 0; q < 4; q++) {
            const float2 f0 = __half22float2(h0[q]);
            const float2 f1 = __half22float2(h1[q]);
            acc[2 * q]     += p0 * f0.x + p1 * f1.x;
            acc[2 * q + 1] += p0 * f0.y + p1 * f1.y;
        }
    }

    // den: all 32 lanes summed = 8x true sum (8 lanes per group) -> /8 later
#pragma unroll
    for (int o = 16; o; o >>= 1) den += __shfl_xor_sync(0xffffffffu, den, o);
    if (lane == 0) fred[w] = den;

    const int part = (w << 2) + g;  // 0..31
#pragma unroll
    for (int q = 0; q < 8; q++) acc_red[part][s8 * 8 + q] = acc[q];
    __syncthreads();
    if (tid == 0) {
        float s = 0.f;
        for (int q = 0; q < 8; q++) s += fred[q];
        den_s = s * 0.125f;
    }

    // tree reduce 32 partials -> 4 -> 1, fixed order (deterministic)
    const int f = tid & 63;
    const int c4 = tid >> 6;  // 0..3
    float sp = 0.f;
#pragma unroll
    for (int q = 0; q < 8; q++) sp += acc_red[c4 * 8 + q][f];
    fin[c4][f] = sp;
    __syncthreads();

    if (tid < OUT_F) {
        float vv = (fin[0][tid] + fin[1][tid] + fin[2][tid] + fin[3][tid]) / den_s;
        vv = vv > 0.f ? vv : expm1f(vv);  // ELU
        out[(size_t)i * OUT_F + tid] = vv;
    }
}

// ---------------------------------------------------------------------------
// inputs: h [8192,256] f32, adj [8192,8192] f32, W [256,64] f32, a [128,1] f32
// output: [8192,64] f32
// ---------------------------------------------------------------------------
extern "C" void kernel_launch(void* const* d_in, const int* in_sizes, int n_in,
                              void* d_out, int out_size) {
    const float* h   = (const float*)d_in[0];
    const float* adj = (const float*)d_in[1];
    const float* W   = (const float*)d_in[2];
    const float* a   = (const float*)d_in[3];
    float* out = (float*)d_out;

    wh_kernel<<<NWHBLK, 256>>>(h, W, a);
    attn_kernel<<<N_NODES, 256>>>(adj, out);
}